// round 9
// baseline (speedup 1.0000x reference)
#include <cuda_runtime.h>
#include <cuda_bf16.h>
#include <cuda_fp16.h>
#include <math.h>
#include <stdint.h>

#define NN 8192
#define BB 4
#define CC 256
#define EE 262144
#define MM (BB*NN)
#define KK 512          // GEMM K = 2*CC  ([x | y])

// ---- static scratch ----
__device__ int      g_is32;
__device__ int      g_cnt[NN];          // zero-initialized at load; re-zeroed by k_mma tail
__device__ int      g_rowptr[NN + 1];
__device__ int      g_cursor[NN];
__device__ float    g_invdeg[NN];
__device__ int      g_col[EE];
__device__ uint32_t g_xh[(size_t)MM * (CC/2)];     // x in fp16 (half2-packed), for agg
__device__ uint32_t g_ahl[(size_t)MM * KK];        // GEMM A, bf16 split packed: [m][k] (hi | lo<<16)
__device__ uint32_t g_whl[(size_t)CC * KK];        // W^T split: [n][k] packed (hi | lo<<16)
__device__ float    g_bias[CC];                    // b_self + b_neigh

__device__ __forceinline__ uint32_t pack_split(float v) {
    __nv_bfloat16 h = __float2bfloat16(v);
    __nv_bfloat16 l = __float2bfloat16(v - __bfloat162float(h));
    return (uint32_t)__bfloat16_as_ushort(h) | ((uint32_t)__bfloat16_as_ushort(l) << 16);
}

__device__ __forceinline__ uint32_t prmt(uint32_t a, uint32_t b, uint32_t s) {
    uint32_t d;
    asm("prmt.b32 %0, %1, %2, %3;" : "=r"(d) : "r"(a), "r"(b), "r"(s));
    return d;
}

__device__ __forceinline__ int edge_at(const void* ei, int idx, int is32) {
    return is32 ? ((const int*)ei)[idx] : (int)((const long long*)ei)[idx];
}

// ===== fused prep: detect + x->fp16 + x->split + W prep + bias + edge COUNT =====
// g_cnt must be zero on entry: guaranteed (zero-init at load; k_mma tail re-zeroes).
__global__ __launch_bounds__(256)
void k_prep(const float* __restrict__ x, const void* __restrict__ ei,
            const float* __restrict__ Ws, const float* __restrict__ Wn,
            const float* __restrict__ bs, const float* __restrict__ bn) {
    const int tid = threadIdx.x;
    const int bid = blockIdx.x;
    const int i = bid * 256 + tid;    // 0 .. MM*CC/4-1  (2,097,152)
    __shared__ int s_is32;

    // edge-dtype detect (blocks that count need it; block 0 publishes it)
    if (bid < EE / 256) {
        if (tid < 32) {
            const unsigned long long* e64 = (const unsigned long long*)ei;
            unsigned long long o = (e64[tid] >> 32) | (e64[32 + tid] >> 32);
            unsigned m = __ballot_sync(0xffffffffu, o != 0ull);
            if (tid == 0) s_is32 = (m != 0u) ? 1 : 0;
        }
        __syncthreads();
    }

    // x conversion: 4 elems per thread
    {
        float4 v = *(const float4*)(x + (size_t)i * 4);
        __half2 h0 = __floats2half2_rn(v.x, v.y);
        __half2 h1 = __floats2half2_rn(v.z, v.w);
        uint2 o;
        o.x = *(uint32_t*)&h0;
        o.y = *(uint32_t*)&h1;
        *(uint2*)(g_xh + (size_t)i * 2) = o;

        int e4 = i * 4;
        int m = e4 >> 8;          // /CC
        int k = e4 & 255;         // %CC
        uint4 pk;
        pk.x = pack_split(v.x);
        pk.y = pack_split(v.y);
        pk.z = pack_split(v.z);
        pk.w = pack_split(v.w);
        *(uint4*)(g_ahl + (size_t)m * KK + k) = pk;
    }

    // edge counting (first EE/256 blocks, one edge per thread)
    if (bid < EE / 256) {
        int is32 = s_is32;
        int src = edge_at(ei, i, is32);
        if (src >= 0 && src < NN) atomicAdd(&g_cnt[src], 1);
        if (i == 0) g_is32 = is32;
    }

    if (i < KK * CC) {            // W prep
        int k = i / CC;
        int n = i % CC;
        float w = (k < CC) ? Ws[(size_t)k * CC + n] : Wn[(size_t)(k - CC) * CC + n];
        g_whl[(size_t)n * KK + k] = pack_split(w);
    }

    if (i < CC) g_bias[i] = bs[i] + bn[i];
}

// ================= CSR scan + scatter =================
__global__ __launch_bounds__(1024)
void k_scan() {      // 1024 threads, 8 elems each
    __shared__ int wsum[32];
    int tid = threadIdx.x;
    int lane = tid & 31, warp = tid >> 5;
    int base = tid * 8;
    int local[8];
    int s = 0;
#pragma unroll
    for (int k = 0; k < 8; k++) { local[k] = s; s += g_cnt[base + k]; }
    int inc = s;
#pragma unroll
    for (int off = 1; off < 32; off <<= 1) {
        int v = __shfl_up_sync(0xffffffffu, inc, off);
        if (lane >= off) inc += v;
    }
    if (lane == 31) wsum[warp] = inc;
    __syncthreads();
    if (tid < 32) {
        int v = wsum[tid];
        int inc2 = v;
#pragma unroll
        for (int off = 1; off < 32; off <<= 1) {
            int u = __shfl_up_sync(0xffffffffu, inc2, off);
            if (tid >= off) inc2 += u;
        }
        wsum[tid] = inc2 - v;   // exclusive
    }
    __syncthreads();
    int off0 = wsum[warp] + (inc - s);
#pragma unroll
    for (int k = 0; k < 8; k++) {
        int rp = off0 + local[k];
        g_rowptr[base + k] = rp;
        g_cursor[base + k] = rp;
        g_invdeg[base + k] = 1.0f / (float)(g_cnt[base + k] + 1);
    }
    if (tid == 1023) g_rowptr[NN] = off0 + s;
}

__global__ void k_scatter(const void* __restrict__ ei) {
    int base = (blockIdx.x * blockDim.x + threadIdx.x) * 4;
    int is32 = g_is32;
    int src[4], dst[4];
#pragma unroll
    for (int q = 0; q < 4; q++) {
        src[q] = edge_at(ei, base + q, is32);
        dst[q] = edge_at(ei, EE + base + q, is32);
    }
#pragma unroll
    for (int q = 0; q < 4; q++) {
        if (src[q] >= 0 && src[q] < NN && dst[q] >= 0 && dst[q] < NN) {
            int pos = atomicAdd(&g_cursor[src[q]], 1);
            if (pos >= 0 && pos < EE) g_col[pos] = dst[q];
        }
    }
}

// ===== neighbor aggregation: y = A_hat @ x (fp16 reads, packed-split writes) =====
__global__ __launch_bounds__(128)
void k_agg() {
    int i = blockIdx.x;           // node
    int c2 = threadIdx.x;         // channel pair 0..127
    int start = g_rowptr[i];
    int end = g_rowptr[i + 1];
    float inv = g_invdeg[i];

    const uint32_t* x0 = g_xh + (size_t)(0 * NN) * (CC/2) + c2;
    const uint32_t* x1 = g_xh + (size_t)(1 * NN) * (CC/2) + c2;
    const uint32_t* x2 = g_xh + (size_t)(2 * NN) * (CC/2) + c2;
    const uint32_t* x3 = g_xh + (size_t)(3 * NN) * (CC/2) + c2;

    float2 a0, a1, a2, a3;
    {   // self loop
        size_t o = (size_t)i * (CC/2);
        a0 = __half22float2(*(const __half2*)&x0[o]);
        a1 = __half22float2(*(const __half2*)&x1[o]);
        a2 = __half22float2(*(const __half2*)&x2[o]);
        a3 = __half22float2(*(const __half2*)&x3[o]);
    }

#define ACC_EDGE(OFF)                                                  \
    {                                                                  \
        float2 t;                                                      \
        t = __half22float2(*(const __half2*)&x0[OFF]); a0.x += t.x; a0.y += t.y; \
        t = __half22float2(*(const __half2*)&x1[OFF]); a1.x += t.x; a1.y += t.y; \
        t = __half22float2(*(const __half2*)&x2[OFF]); a2.x += t.x; a2.y += t.y; \
        t = __half22float2(*(const __half2*)&x3[OFF]); a3.x += t.x; a3.y += t.y; \
    }

    int p = start;
    for (; p + 1 < end; p += 2) {
        size_t o0 = (size_t)g_col[p] * (CC/2);
        size_t o1 = (size_t)g_col[p + 1] * (CC/2);
        ACC_EDGE(o0);
        ACC_EDGE(o1);
    }
    if (p < end) {
        size_t o = (size_t)g_col[p] * (CC/2);
        ACC_EDGE(o);
    }
#undef ACC_EDGE

    int c = CC + c2 * 2;          // y occupies cols 256..511 of g_ahl
    uint2 w0, w1, w2, w3;
    w0.x = pack_split(a0.x * inv); w0.y = pack_split(a0.y * inv);
    w1.x = pack_split(a1.x * inv); w1.y = pack_split(a1.y * inv);
    w2.x = pack_split(a2.x * inv); w2.y = pack_split(a2.y * inv);
    w3.x = pack_split(a3.x * inv); w3.y = pack_split(a3.y * inv);
    *(uint2*)(g_ahl + ((size_t)(0 * NN + i)) * KK + c) = w0;
    *(uint2*)(g_ahl + ((size_t)(1 * NN + i)) * KK + c) = w1;
    *(uint2*)(g_ahl + ((size_t)(2 * NN + i)) * KK + c) = w2;
    *(uint2*)(g_ahl + ((size_t)(3 * NN + i)) * KK + c) = w3;
}

// ================= tensor-core GEMM + bias + GELU =================
#define GBM 128
#define GBN 128
#define GBK 32
#define KTILES (KK / GBK)   // 16
#define APAD 8              // row stride 40 bf16 = 80B: 16B-aligned, ldmatrix conflict-free

__device__ __forceinline__ void mma16816(float* c, const uint32_t* a, const uint32_t* b) {
    asm volatile(
        "mma.sync.aligned.m16n8k16.row.col.f32.bf16.bf16.f32 "
        "{%0,%1,%2,%3}, {%4,%5,%6,%7}, {%8,%9}, {%0,%1,%2,%3};"
        : "+f"(c[0]), "+f"(c[1]), "+f"(c[2]), "+f"(c[3])
        : "r"(a[0]), "r"(a[1]), "r"(a[2]), "r"(a[3]), "r"(b[0]), "r"(b[1]));
}

#define LDSM4(r0, r1, r2, r3, addr) \
    asm volatile("ldmatrix.sync.aligned.m8n8.x4.shared.b16 {%0,%1,%2,%3}, [%4];" \
                 : "=r"(r0), "=r"(r1), "=r"(r2), "=r"(r3) : "r"(addr))

__device__ __forceinline__ float gelu_exact(float z) {
    return 0.5f * z * (1.0f + erff(z * 0.70710678118654752440f));
}

__global__ __launch_bounds__(256, 2)
void k_mma(float* __restrict__ out) {
    __shared__ __align__(16) __nv_bfloat16 Ah[GBM][GBK + APAD];
    __shared__ __align__(16) __nv_bfloat16 Al[GBM][GBK + APAD];
    __shared__ __align__(16) __nv_bfloat16 Bh[GBN][GBK + APAD];
    __shared__ __align__(16) __nv_bfloat16 Bl[GBN][GBK + APAD];

    const int tid = threadIdx.x;
    const int lane = tid & 31;
    const int warp = tid >> 5;
    const int warp_m = warp & 3;        // 4 warps along M (32 rows each)
    const int warp_n = warp >> 2;       // 2 warps along N (64 cols each)
    const int n0 = blockIdx.x * GBN;    // 0 or 128
    const int m0 = blockIdx.y * GBM;

    const int a_r = tid >> 3;           // 0..31
    const int a_k = (tid & 7) * 4;      // 0,4,...,28
    const int w_n = tid >> 1;           // 0..127
    const int w_k = (tid & 1) * 16;     // 0 or 16

    // zero g_cnt for the NEXT kernel_launch call (invariant: g_cnt==0 on entry to k_prep)
    if (blockIdx.x == 0 && blockIdx.y < 32) g_cnt[blockIdx.y * 256 + tid] = 0;

    float acc[2][8][4];
#pragma unroll
    for (int i = 0; i < 2; i++)
#pragma unroll
        for (int j = 0; j < 8; j++)
#pragma unroll
            for (int q = 0; q < 4; q++) acc[i][j][q] = 0.0f;

    uint4 pa[4];
    uint4 pw[4];

    // ---- prefetch tile 0 ----
#pragma unroll
    for (int p = 0; p < 4; p++)
        pa[p] = *(const uint4*)(g_ahl + (size_t)(m0 + p * 32 + a_r) * KK + a_k);
    {
        const uint32_t* wp = g_whl + (size_t)(n0 + w_n) * KK + w_k;
#pragma unroll
        for (int q = 0; q < 4; q++) pw[q] = *(const uint4*)(wp + q * 4);
    }

    for (int kt = 0; kt < KTILES; kt++) {
        // ---- store smem: PRMT-unpack hi/lo pairs, STS.64 ----
#pragma unroll
        for (int p = 0; p < 4; p++) {
            int r = p * 32 + a_r;
            uint2 hi, lo;
            hi.x = prmt(pa[p].x, pa[p].y, 0x5410u);
            hi.y = prmt(pa[p].z, pa[p].w, 0x5410u);
            lo.x = prmt(pa[p].x, pa[p].y, 0x7632u);
            lo.y = prmt(pa[p].z, pa[p].w, 0x7632u);
            *(uint2*)((char*)&Ah[r][0] + a_k * 2) = hi;
            *(uint2*)((char*)&Al[r][0] + a_k * 2) = lo;
        }
#pragma unroll
        for (int q = 0; q < 4; q++) {
            int kk = w_k + q * 4;
            uint2 hi, lo;
            hi.x = prmt(pw[q].x, pw[q].y, 0x5410u);
            hi.y = prmt(pw[q].z, pw[q].w, 0x5410u);
            lo.x = prmt(pw[q].x, pw[q].y, 0x7632u);
            lo.y = prmt(pw[q].z, pw[q].w, 0x7632u);
            *(uint2*)((char*)&Bh[w_n][0] + kk * 2) = hi;
            *(uint2*)((char*)&Bl[w_n][0] + kk * 2) = lo;
        }
        __syncthreads();

        // ---- prefetch next tile ----
        if (kt + 1 < KTILES) {
            int k0 = (kt + 1) * GBK;
#pragma unroll
            for (int p = 0; p < 4; p++)
                pa[p] = *(const uint4*)(g_ahl + (size_t)(m0 + p * 32 + a_r) * KK + k0 + a_k);
            const uint32_t* wp = g_whl + (size_t)(n0 + w_n) * KK + k0 + w_k;
#pragma unroll
            for (int q = 0; q < 4; q++) pw[q] = *(const uint4*)(wp + q * 4);
        }

        // ---- compute: 2 k16 steps ----
#pragma unroll
        for (int s = 0; s < 2; s++) {
            const int kb = s * 16;
            const int sub = lane >> 3;
            const int l8 = lane & 7;
            const int arow_off = (sub & 1) * 8 + l8;
            const int acol_off = kb + (sub >> 1) * 8;

            uint32_t ah[2][4], al[2][4];
#pragma unroll
            for (int mt = 0; mt < 2; mt++) {
                int rbase = warp_m * 32 + mt * 16;
                uint32_t ad_h = (uint32_t)__cvta_generic_to_shared(
                    &Ah[rbase + arow_off][acol_off]);
                LDSM4(ah[mt][0], ah[mt][1], ah[mt][2], ah[mt][3], ad_h);
                uint32_t ad_l = (uint32_t)__cvta_generic_to_shared(
                    &Al[rbase + arow_off][acol_off]);
                LDSM4(al[mt][0], al[mt][1], al[mt][2], al[mt][3], ad_l);
            }

            uint32_t bh[8][2], bl[8][2];
#pragma unroll
            for (int np = 0; np < 4; np++) {
                int nbase = warp_n * 64 + np * 16;
                uint32_t r0, r1, r2, r3;
                uint32_t bd_h = (uint32_t)__cvta_generic_to_shared(
                    &Bh[nbase + arow_off][acol_off]);
                LDSM4(r0, r1, r2, r3, bd_h);
                bh[2 * np][0] = r0; bh[2 * np][1] = r2;
                bh[2 * np + 1][0] = r1; bh[2 * np + 1][1] = r3;
                uint32_t bd_l = (uint32_t)__cvta_generic_to_shared(
                    &Bl[nbase + arow_off][acol_off]);
                LDSM4(r0, r1, r2, r3, bd_l);
                bl[2 * np][0] = r0; bl[2 * np][1] = r2;
                bl[2 * np + 1][0] = r1; bl[2 * np + 1][1] = r3;
            }

#pragma unroll
            for (int mt = 0; mt < 2; mt++)
#pragma unroll
                for (int nt = 0; nt < 8; nt++) {
                    mma16816(acc[mt][nt], ah[mt], bh[nt]);
                    mma16816(acc[mt][nt], ah[mt], bl[nt]);
                    mma16816(acc[mt][nt], al[mt], bh[nt]);
                }
        }
        __syncthreads();
    }

    // ---- epilogue: bias + gelu, direct store ----
    const int g = lane >> 2;
    const int q2 = (lane & 3) * 2;
#pragma unroll
    for (int nt = 0; nt < 8; nt++) {
        int col = n0 + warp_n * 64 + nt * 8 + q2;
        float bias0 = g_bias[col];
        float bias1 = g_bias[col + 1];
#pragma unroll
        for (int mt = 0; mt < 2; mt++) {
            int row = m0 + warp_m * 32 + mt * 16 + g;
            float2 o0, o1;
            o0.x = gelu_exact(acc[mt][nt][0] + bias0);
            o0.y = gelu_exact(acc[mt][nt][1] + bias1);
            o1.x = gelu_exact(acc[mt][nt][2] + bias0);
            o1.y = gelu_exact(acc[mt][nt][3] + bias1);
            *(float2*)(out + (size_t)row * CC + col) = o0;
            *(float2*)(out + (size_t)(row + 8) * CC + col) = o1;
        }
    }
}

// ================= launch =================
extern "C" void kernel_launch(void* const* d_in, const int* in_sizes, int n_in,
                              void* d_out, int out_size) {
    const float* x = 0; const void* ei = 0;
    const float* Ws = 0; const float* bsv = 0;
    const float* Wn = 0; const float* bnv = 0;
    for (int i = 0; i < n_in; i++) {
        int s = in_sizes[i];
        if (s == BB * NN * CC)      x = (const float*)d_in[i];
        else if (s == 2 * EE)       ei = d_in[i];
        else if (s == CC * CC) { if (!Ws) Ws = (const float*)d_in[i]; else Wn = (const float*)d_in[i]; }
        else if (s == CC)      { if (!bsv) bsv = (const float*)d_in[i]; else bnv = (const float*)d_in[i]; }
    }
    float* out = (float*)d_out;

    k_prep<<<(MM * CC / 4) / 256, 256>>>(x, ei, Ws, Wn, bsv, bnv);
    k_scan<<<1, 1024>>>();
    k_scatter<<<EE / 1024, 256>>>(ei);

    k_agg<<<NN, 128>>>();

    dim3 ggrid(CC / GBN, MM / GBM);   // (2, 256)
    k_mma<<<ggrid, 256>>>(out);
}

// round 10
// speedup vs baseline: 1.1420x; 1.1420x over previous
#include <cuda_runtime.h>
#include <cuda_bf16.h>
#include <cuda_fp16.h>
#include <math.h>
#include <stdint.h>

#define NN 8192
#define BB 4
#define CC 256
#define EE 262144
#define MM (BB*NN)
#define KK 512          // GEMM K = 2*CC  ([x | y])

// ---- static scratch ----
__device__ int      g_is32;
__device__ int      g_cnt[NN];          // zero-initialized at load; re-zeroed by k_mma tail
__device__ int      g_rowptr[NN + 1];
__device__ int      g_cursor[NN];
__device__ float    g_invdeg[NN];
__device__ int      g_col[EE];
__device__ uint32_t g_xh[(size_t)MM * (CC/2)];     // x in fp16 (half2-packed), for agg
__device__ uint32_t g_ahl[(size_t)MM * KK];        // GEMM A, bf16 split packed: [m][k] (hi | lo<<16)
__device__ uint32_t g_whl[(size_t)CC * KK];        // W^T split: [n][k] packed (hi | lo<<16)
__device__ float    g_bias[CC];                    // b_self + b_neigh

__device__ __forceinline__ uint32_t pack_split(float v) {
    __nv_bfloat16 h = __float2bfloat16(v);
    __nv_bfloat16 l = __float2bfloat16(v - __bfloat162float(h));
    return (uint32_t)__bfloat16_as_ushort(h) | ((uint32_t)__bfloat16_as_ushort(l) << 16);
}

__device__ __forceinline__ uint32_t prmt(uint32_t a, uint32_t b, uint32_t s) {
    uint32_t d;
    asm("prmt.b32 %0, %1, %2, %3;" : "=r"(d) : "r"(a), "r"(b), "r"(s));
    return d;
}

__device__ __forceinline__ int edge_at(const void* ei, int idx, int is32) {
    return is32 ? ((const int*)ei)[idx] : (int)((const long long*)ei)[idx];
}

// ===== fused prep: detect + x->fp16 + x->split + W prep + bias + edge COUNT =====
// g_cnt must be zero on entry: guaranteed (zero-init at load; k_mma tail re-zeroes).
__global__ __launch_bounds__(256)
void k_prep(const float* __restrict__ x, const void* __restrict__ ei,
            const float* __restrict__ Ws, const float* __restrict__ Wn,
            const float* __restrict__ bs, const float* __restrict__ bn) {
    const int tid = threadIdx.x;
    const int bid = blockIdx.x;
    const int i = bid * 256 + tid;    // 0 .. MM*CC/4-1  (2,097,152)
    __shared__ int s_is32;

    // edge-dtype detect (blocks that count need it)
    if (bid < EE / 256) {
        if (tid < 32) {
            const unsigned long long* e64 = (const unsigned long long*)ei;
            unsigned long long o = (e64[tid] >> 32) | (e64[32 + tid] >> 32);
            unsigned m = __ballot_sync(0xffffffffu, o != 0ull);
            if (tid == 0) s_is32 = (m != 0u) ? 1 : 0;
        }
        __syncthreads();
    }

    // x conversion: 4 elems per thread
    {
        float4 v = *(const float4*)(x + (size_t)i * 4);
        __half2 h0 = __floats2half2_rn(v.x, v.y);
        __half2 h1 = __floats2half2_rn(v.z, v.w);
        uint2 o;
        o.x = *(uint32_t*)&h0;
        o.y = *(uint32_t*)&h1;
        *(uint2*)(g_xh + (size_t)i * 2) = o;

        int e4 = i * 4;
        int m = e4 >> 8;          // /CC
        int k = e4 & 255;         // %CC
        uint4 pk;
        pk.x = pack_split(v.x);
        pk.y = pack_split(v.y);
        pk.z = pack_split(v.z);
        pk.w = pack_split(v.w);
        *(uint4*)(g_ahl + (size_t)m * KK + k) = pk;
    }

    // edge counting (first EE/256 blocks, one edge per thread)
    if (bid < EE / 256) {
        int is32 = s_is32;
        int src = edge_at(ei, i, is32);
        if (src >= 0 && src < NN) atomicAdd(&g_cnt[src], 1);
        if (i == 0) g_is32 = is32;
    }

    if (i < KK * CC) {            // W prep
        int k = i / CC;
        int n = i % CC;
        float w = (k < CC) ? Ws[(size_t)k * CC + n] : Wn[(size_t)(k - CC) * CC + n];
        g_whl[(size_t)n * KK + k] = pack_split(w);
    }

    if (i < CC) g_bias[i] = bs[i] + bn[i];
}

// ================= CSR scan + scatter =================
__global__ __launch_bounds__(1024)
void k_scan() {      // 1024 threads, 8 elems each
    __shared__ int wsum[32];
    int tid = threadIdx.x;
    int lane = tid & 31, warp = tid >> 5;
    int base = tid * 8;
    int local[8];
    int s = 0;
#pragma unroll
    for (int k = 0; k < 8; k++) { local[k] = s; s += g_cnt[base + k]; }
    int inc = s;
#pragma unroll
    for (int off = 1; off < 32; off <<= 1) {
        int v = __shfl_up_sync(0xffffffffu, inc, off);
        if (lane >= off) inc += v;
    }
    if (lane == 31) wsum[warp] = inc;
    __syncthreads();
    if (tid < 32) {
        int v = wsum[tid];
        int inc2 = v;
#pragma unroll
        for (int off = 1; off < 32; off <<= 1) {
            int u = __shfl_up_sync(0xffffffffu, inc2, off);
            if (tid >= off) inc2 += u;
        }
        wsum[tid] = inc2 - v;   // exclusive
    }
    __syncthreads();
    int off0 = wsum[warp] + (inc - s);
#pragma unroll
    for (int k = 0; k < 8; k++) {
        int rp = off0 + local[k];
        g_rowptr[base + k] = rp;
        g_cursor[base + k] = rp;
        g_invdeg[base + k] = 1.0f / (float)(g_cnt[base + k] + 1);
    }
    if (tid == 1023) g_rowptr[NN] = off0 + s;
}

__global__ void k_scatter(const void* __restrict__ ei) {
    int base = (blockIdx.x * blockDim.x + threadIdx.x) * 4;
    int is32 = g_is32;
    int src[4], dst[4];
#pragma unroll
    for (int q = 0; q < 4; q++) {
        src[q] = edge_at(ei, base + q, is32);
        dst[q] = edge_at(ei, EE + base + q, is32);
    }
#pragma unroll
    for (int q = 0; q < 4; q++) {
        if (src[q] >= 0 && src[q] < NN && dst[q] >= 0 && dst[q] < NN) {
            int pos = atomicAdd(&g_cursor[src[q]], 1);
            if (pos >= 0 && pos < EE) g_col[pos] = dst[q];
        }
    }
}

// ===== neighbor aggregation: y = A_hat @ x (fp16 reads, packed-split writes) =====
__global__ __launch_bounds__(128)
void k_agg() {
    int i = blockIdx.x;           // node
    int c2 = threadIdx.x;         // channel pair 0..127
    int start = g_rowptr[i];
    int end = g_rowptr[i + 1];
    float inv = g_invdeg[i];

    const uint32_t* x0 = g_xh + (size_t)(0 * NN) * (CC/2) + c2;
    const uint32_t* x1 = g_xh + (size_t)(1 * NN) * (CC/2) + c2;
    const uint32_t* x2 = g_xh + (size_t)(2 * NN) * (CC/2) + c2;
    const uint32_t* x3 = g_xh + (size_t)(3 * NN) * (CC/2) + c2;

    float2 a0, a1, a2, a3;
    {   // self loop
        size_t o = (size_t)i * (CC/2);
        a0 = __half22float2(*(const __half2*)&x0[o]);
        a1 = __half22float2(*(const __half2*)&x1[o]);
        a2 = __half22float2(*(const __half2*)&x2[o]);
        a3 = __half22float2(*(const __half2*)&x3[o]);
    }

#define ACC_EDGE(OFF)                                                  \
    {                                                                  \
        float2 t;                                                      \
        t = __half22float2(*(const __half2*)&x0[OFF]); a0.x += t.x; a0.y += t.y; \
        t = __half22float2(*(const __half2*)&x1[OFF]); a1.x += t.x; a1.y += t.y; \
        t = __half22float2(*(const __half2*)&x2[OFF]); a2.x += t.x; a2.y += t.y; \
        t = __half22float2(*(const __half2*)&x3[OFF]); a3.x += t.x; a3.y += t.y; \
    }

    int p = start;
    for (; p + 1 < end; p += 2) {
        size_t o0 = (size_t)g_col[p] * (CC/2);
        size_t o1 = (size_t)g_col[p + 1] * (CC/2);
        ACC_EDGE(o0);
        ACC_EDGE(o1);
    }
    if (p < end) {
        size_t o = (size_t)g_col[p] * (CC/2);
        ACC_EDGE(o);
    }
#undef ACC_EDGE

    int c = CC + c2 * 2;          // y occupies cols 256..511 of g_ahl
    uint2 w0, w1, w2, w3;
    w0.x = pack_split(a0.x * inv); w0.y = pack_split(a0.y * inv);
    w1.x = pack_split(a1.x * inv); w1.y = pack_split(a1.y * inv);
    w2.x = pack_split(a2.x * inv); w2.y = pack_split(a2.y * inv);
    w3.x = pack_split(a3.x * inv); w3.y = pack_split(a3.y * inv);
    *(uint2*)(g_ahl + ((size_t)(0 * NN + i)) * KK + c) = w0;
    *(uint2*)(g_ahl + ((size_t)(1 * NN + i)) * KK + c) = w1;
    *(uint2*)(g_ahl + ((size_t)(2 * NN + i)) * KK + c) = w2;
    *(uint2*)(g_ahl + ((size_t)(3 * NN + i)) * KK + c) = w3;
}

// ================= tensor-core GEMM + bias + GELU =================
#define GBM 128
#define GBN 128
#define GBK 32
#define KTILES (KK / GBK)   // 16
#define APAD 8              // row stride 40 bf16 = 80B: 16B-aligned, ldmatrix conflict-free

__device__ __forceinline__ void mma16816(float* c, const uint32_t* a, const uint32_t* b) {
    asm volatile(
        "mma.sync.aligned.m16n8k16.row.col.f32.bf16.bf16.f32 "
        "{%0,%1,%2,%3}, {%4,%5,%6,%7}, {%8,%9}, {%0,%1,%2,%3};"
        : "+f"(c[0]), "+f"(c[1]), "+f"(c[2]), "+f"(c[3])
        : "r"(a[0]), "r"(a[1]), "r"(a[2]), "r"(a[3]), "r"(b[0]), "r"(b[1]));
}

#define LDSM4(r0, r1, r2, r3, addr) \
    asm volatile("ldmatrix.sync.aligned.m8n8.x4.shared.b16 {%0,%1,%2,%3}, [%4];" \
                 : "=r"(r0), "=r"(r1), "=r"(r2), "=r"(r3) : "r"(addr))

__device__ __forceinline__ float gelu_exact(float z) {
    return 0.5f * z * (1.0f + erff(z * 0.70710678118654752440f));
}

__global__ __launch_bounds__(256, 1)
void k_mma(float* __restrict__ out) {
    __shared__ __align__(16) __nv_bfloat16 Ah[GBM][GBK + APAD];
    __shared__ __align__(16) __nv_bfloat16 Al[GBM][GBK + APAD];
    __shared__ __align__(16) __nv_bfloat16 Bh[GBN][GBK + APAD];
    __shared__ __align__(16) __nv_bfloat16 Bl[GBN][GBK + APAD];

    const int tid = threadIdx.x;
    const int lane = tid & 31;
    const int warp = tid >> 5;
    const int warp_m = warp & 3;        // 4 warps along M (32 rows each)
    const int warp_n = warp >> 2;       // 2 warps along N (64 cols each)
    const int n0 = blockIdx.x * GBN;    // 0 or 128
    const int m0 = blockIdx.y * GBM;

    const int a_r = tid >> 3;           // 0..31
    const int a_k = (tid & 7) * 4;      // 0,4,...,28
    const int w_n = tid >> 1;           // 0..127
    const int w_k = (tid & 1) * 16;     // 0 or 16

    // zero g_cnt for the NEXT kernel_launch call (invariant: g_cnt==0 on entry to k_prep)
    if (blockIdx.x == 0 && blockIdx.y < 32) g_cnt[blockIdx.y * 256 + tid] = 0;

    float acc[2][8][4];
#pragma unroll
    for (int i = 0; i < 2; i++)
#pragma unroll
        for (int j = 0; j < 8; j++)
#pragma unroll
            for (int q = 0; q < 4; q++) acc[i][j][q] = 0.0f;

    uint4 pa[4];
    uint4 pw[4];

    // ---- prefetch tile 0 ----
#pragma unroll
    for (int p = 0; p < 4; p++)
        pa[p] = *(const uint4*)(g_ahl + (size_t)(m0 + p * 32 + a_r) * KK + a_k);
    {
        const uint32_t* wp = g_whl + (size_t)(n0 + w_n) * KK + w_k;
#pragma unroll
        for (int q = 0; q < 4; q++) pw[q] = *(const uint4*)(wp + q * 4);
    }

    for (int kt = 0; kt < KTILES; kt++) {
        // ---- store smem: PRMT-unpack hi/lo pairs, STS.64 ----
#pragma unroll
        for (int p = 0; p < 4; p++) {
            int r = p * 32 + a_r;
            uint2 hi, lo;
            hi.x = prmt(pa[p].x, pa[p].y, 0x5410u);
            hi.y = prmt(pa[p].z, pa[p].w, 0x5410u);
            lo.x = prmt(pa[p].x, pa[p].y, 0x7632u);
            lo.y = prmt(pa[p].z, pa[p].w, 0x7632u);
            *(uint2*)((char*)&Ah[r][0] + a_k * 2) = hi;
            *(uint2*)((char*)&Al[r][0] + a_k * 2) = lo;
        }
#pragma unroll
        for (int q = 0; q < 4; q++) {
            int kk = w_k + q * 4;
            uint2 hi, lo;
            hi.x = prmt(pw[q].x, pw[q].y, 0x5410u);
            hi.y = prmt(pw[q].z, pw[q].w, 0x5410u);
            lo.x = prmt(pw[q].x, pw[q].y, 0x7632u);
            lo.y = prmt(pw[q].z, pw[q].w, 0x7632u);
            *(uint2*)((char*)&Bh[w_n][0] + kk * 2) = hi;
            *(uint2*)((char*)&Bl[w_n][0] + kk * 2) = lo;
        }
        __syncthreads();

        // ---- prefetch next tile ----
        if (kt + 1 < KTILES) {
            int k0 = (kt + 1) * GBK;
#pragma unroll
            for (int p = 0; p < 4; p++)
                pa[p] = *(const uint4*)(g_ahl + (size_t)(m0 + p * 32 + a_r) * KK + k0 + a_k);
            const uint32_t* wp = g_whl + (size_t)(n0 + w_n) * KK + k0 + w_k;
#pragma unroll
            for (int q = 0; q < 4; q++) pw[q] = *(const uint4*)(wp + q * 4);
        }

        // ---- compute: 2 k16 steps ----
#pragma unroll
        for (int s = 0; s < 2; s++) {
            const int kb = s * 16;
            const int sub = lane >> 3;
            const int l8 = lane & 7;
            const int arow_off = (sub & 1) * 8 + l8;
            const int acol_off = kb + (sub >> 1) * 8;

            uint32_t ah[2][4], al[2][4];
#pragma unroll
            for (int mt = 0; mt < 2; mt++) {
                int rbase = warp_m * 32 + mt * 16;
                uint32_t ad_h = (uint32_t)__cvta_generic_to_shared(
                    &Ah[rbase + arow_off][acol_off]);
                LDSM4(ah[mt][0], ah[mt][1], ah[mt][2], ah[mt][3], ad_h);
                uint32_t ad_l = (uint32_t)__cvta_generic_to_shared(
                    &Al[rbase + arow_off][acol_off]);
                LDSM4(al[mt][0], al[mt][1], al[mt][2], al[mt][3], ad_l);
            }

            uint32_t bh[8][2], bl[8][2];
#pragma unroll
            for (int np = 0; np < 4; np++) {
                int nbase = warp_n * 64 + np * 16;
                uint32_t r0, r1, r2, r3;
                uint32_t bd_h = (uint32_t)__cvta_generic_to_shared(
                    &Bh[nbase + arow_off][acol_off]);
                LDSM4(r0, r1, r2, r3, bd_h);
                bh[2 * np][0] = r0; bh[2 * np][1] = r2;
                bh[2 * np + 1][0] = r1; bh[2 * np + 1][1] = r3;
                uint32_t bd_l = (uint32_t)__cvta_generic_to_shared(
                    &Bl[nbase + arow_off][acol_off]);
                LDSM4(r0, r1, r2, r3, bd_l);
                bl[2 * np][0] = r0; bl[2 * np][1] = r2;
                bl[2 * np + 1][0] = r1; bl[2 * np + 1][1] = r3;
            }

#pragma unroll
            for (int mt = 0; mt < 2; mt++)
#pragma unroll
                for (int nt = 0; nt < 8; nt++) {
                    mma16816(acc[mt][nt], ah[mt], bh[nt]);
                    mma16816(acc[mt][nt], ah[mt], bl[nt]);
                    mma16816(acc[mt][nt], al[mt], bh[nt]);
                }
        }
        __syncthreads();
    }

    // ---- epilogue: bias + gelu, direct store ----
    const int g = lane >> 2;
    const int q2 = (lane & 3) * 2;
#pragma unroll
    for (int nt = 0; nt < 8; nt++) {
        int col = n0 + warp_n * 64 + nt * 8 + q2;
        float bias0 = g_bias[col];
        float bias1 = g_bias[col + 1];
#pragma unroll
        for (int mt = 0; mt < 2; mt++) {
            int row = m0 + warp_m * 32 + mt * 16 + g;
            float2 o0, o1;
            o0.x = gelu_exact(acc[mt][nt][0] + bias0);
            o0.y = gelu_exact(acc[mt][nt][1] + bias1);
            o1.x = gelu_exact(acc[mt][nt][2] + bias0);
            o1.y = gelu_exact(acc[mt][nt][3] + bias1);
            *(float2*)(out + (size_t)row * CC + col) = o0;
            *(float2*)(out + (size_t)(row + 8) * CC + col) = o1;
        }
    }
}

// ================= launch =================
extern "C" void kernel_launch(void* const* d_in, const int* in_sizes, int n_in,
                              void* d_out, int out_size) {
    const float* x = 0; const void* ei = 0;
    const float* Ws = 0; const float* bsv = 0;
    const float* Wn = 0; const float* bnv = 0;
    for (int i = 0; i < n_in; i++) {
        int s = in_sizes[i];
        if (s == BB * NN * CC)      x = (const float*)d_in[i];
        else if (s == 2 * EE)       ei = d_in[i];
        else if (s == CC * CC) { if (!Ws) Ws = (const float*)d_in[i]; else Wn = (const float*)d_in[i]; }
        else if (s == CC)      { if (!bsv) bsv = (const float*)d_in[i]; else bnv = (const float*)d_in[i]; }
    }
    float* out = (float*)d_out;

    k_prep<<<(MM * CC / 4) / 256, 256>>>(x, ei, Ws, Wn, bsv, bnv);
    k_scan<<<1, 1024>>>();
    k_scatter<<<EE / 1024, 256>>>(ei);

    k_agg<<<NN, 128>>>();

    dim3 ggrid(CC / GBN, MM / GBM);   // (2, 256)
    k_mma<<<ggrid, 256>>>(out);
}